// round 3
// baseline (speedup 1.0000x reference)
#include <cuda_runtime.h>
#include <cuda_fp16.h>
#include <cstdint>

// ----------------------------------------------------------------------------
// AdaAffcell on sm_103 (base ISA only — tcgen05 is rejected by this harness's
// compute_103 PTX target, so the tensor path uses mma.sync HMMA + ldmatrix).
//
//   hx = [h, x]  (B x 256)
//   g = hx @ W_g^T + b_g ; z = hx @ W_a^T + b_a
//   alpha = sigmoid(g) ; h~ = alpha*tanh(z) + (1-alpha)*z ; out = LN(h~)*gamma+beta
//
// One CTA = 128 rows. D[128,256] = A[128,256] @ Wcat[256,256]^T in fp16.
// Wcat rows 0..127 = W_g, 128..255 = W_a, so D col c (g) pairs with col 128+c (z).
// Warp grid 4x4 (512 thr): wm = row block (32 rows), wn = feature block (32 cols),
// each warp holds BOTH the g cols and the matching z cols -> elementwise combine
// in registers; only row statistics cross warps (4KB SMEM reduction).
// ----------------------------------------------------------------------------

#define TILE_M 128
#define EPSV   1e-5f

// fp16 image of Wcat, padded stride 264 halves (ldmatrix conflict-free).
__device__ __align__(16) __half g_Wimg[256 * 264];

// SMEM layout (bytes):
#define SMEM_W     0            // fp16 [256][264] = 135168
#define SMEM_A     135168       // fp16 [128][264] =  67584
#define SMEM_BG    202752       // f32 [128]
#define SMEM_BA    203264
#define SMEM_GAM   203776
#define SMEM_BET   204288
#define SMEM_PSUM  204800       // f32 [128][4]
#define SMEM_PSQ   206848       // f32 [128][4]
#define SMEM_MU    208896       // f32 [128]
#define SMEM_RSTD  209408       // f32 [128]
#define SMEM_TOTAL 209920

static __device__ __forceinline__ uint32_t smem_u32(const void* p) {
    uint32_t a;
    asm("{ .reg .u64 t; cvta.to.shared.u64 t, %1; cvt.u32.u64 %0, t; }"
        : "=r"(a) : "l"(p));
    return a;
}

static __device__ __forceinline__ float tanh_fast(float v) {
    float r;
    asm("tanh.approx.f32 %0, %1;" : "=f"(r) : "f"(v));
    return r;
}

#define LDSM4(r0, r1, r2, r3, addr)                                          \
    asm volatile("ldmatrix.sync.aligned.m8n8.x4.shared.b16 {%0,%1,%2,%3}, [%4];" \
                 : "=r"(r0), "=r"(r1), "=r"(r2), "=r"(r3) : "r"(addr))

#define MMA16816(c, a0, a1, a2, a3, b0, b1)                                  \
    asm volatile("mma.sync.aligned.m16n8k16.row.col.f32.f16.f16.f32 "        \
                 "{%0,%1,%2,%3}, {%4,%5,%6,%7}, {%8,%9}, {%0,%1,%2,%3};"     \
                 : "+f"((c)[0]), "+f"((c)[1]), "+f"((c)[2]), "+f"((c)[3])    \
                 : "r"(a0), "r"(a1), "r"(a2), "r"(a3), "r"(b0), "r"(b1))

// ---------------------------------------------------------------------------
// Prep: Wcat -> fp16 padded image. Row n: n<128 -> W_g[n], else W_a[n-128].
// ---------------------------------------------------------------------------
__global__ void prep_w_kernel(const float* __restrict__ Wa, const float* __restrict__ Wg) {
    int i = blockIdx.x * 256 + threadIdx.x;   // 0..65535
    int n = i >> 8;
    int k = i & 255;
    float v = (n < 128) ? Wg[n * 256 + k] : Wa[(n - 128) * 256 + k];
    g_Wimg[n * 264 + k] = __float2half_rn(v);
}

// ---------------------------------------------------------------------------
// Main kernel: one 128-row tile per CTA, 512 threads (16 warps, 4x4 grid).
// ---------------------------------------------------------------------------
__global__ void __launch_bounds__(512, 1) adaaff_kernel(
    const float* __restrict__ x, const float* __restrict__ h,
    const float* __restrict__ b_a, const float* __restrict__ b_g,
    const float* __restrict__ gamma, const float* __restrict__ beta,
    float* __restrict__ out)
{
    extern __shared__ __align__(16) char smem[];
    const uint32_t smem_base = smem_u32(smem);
    const int tid  = threadIdx.x;
    const int wid  = tid >> 5;
    const int lane = tid & 31;
    const int wm   = wid & 3;     // row block (32 rows)
    const int wn   = wid >> 2;    // feature block (32 cols)
    const int tig  = lane & 3;
    const int gq   = lane >> 2;
    const int row0 = blockIdx.x * TILE_M;

    // Per-feature vectors
    if (tid < 128) {
        *(float*)(smem + SMEM_BG  + tid * 4) = b_g[tid];
        *(float*)(smem + SMEM_BA  + tid * 4) = b_a[tid];
        *(float*)(smem + SMEM_GAM + tid * 4) = gamma[tid];
        *(float*)(smem + SMEM_BET + tid * 4) = beta[tid];
    }

    // W tile: coalesced copy of fp16 image (135168 B = 8448 uint4)
    {
        const uint4* src = (const uint4*)g_Wimg;
        uint4* dst = (uint4*)(smem + SMEM_W);
        #pragma unroll
        for (int i = tid; i < 8448; i += 512) dst[i] = src[i];
    }

    // A tile: fp32 -> fp16, padded stride 264. k<128 = h, k>=128 = x.
    {
        __half* sA = (__half*)(smem + SMEM_A);
        #pragma unroll
        for (int j = 0; j < 8; j++) {
            int i  = tid + j * 512;          // 0..4095
            int m  = i >> 5;
            int k0 = (i & 31) << 2;
            float4 vh = *(const float4*)&h[(size_t)(row0 + m) * 128 + k0];
            __half2 p0 = __floats2half2_rn(vh.x, vh.y);
            __half2 p1 = __floats2half2_rn(vh.z, vh.w);
            *(uint2*)&sA[m * 264 + k0] =
                make_uint2(*(uint32_t*)&p0, *(uint32_t*)&p1);
            float4 vx = *(const float4*)&x[(size_t)(row0 + m) * 128 + k0];
            __half2 q0 = __floats2half2_rn(vx.x, vx.y);
            __half2 q1 = __floats2half2_rn(vx.z, vx.w);
            *(uint2*)&sA[m * 264 + 128 + k0] =
                make_uint2(*(uint32_t*)&q0, *(uint32_t*)&q1);
        }
    }
    __syncthreads();

    // ldmatrix lane addresses (byte offsets advance 32B per k-step)
    uint32_t a_addr[2];
    #pragma unroll
    for (int i = 0; i < 2; i++) {
        int r  = wm * 32 + 16 * i + (lane & 15);
        int kq = (lane >> 4) * 8;
        a_addr[i] = smem_base + SMEM_A + (uint32_t)(r * 264 + kq) * 2;
    }
    uint32_t b_addr[4];
    #pragma unroll
    for (int j2 = 0; j2 < 4; j2++) {
        int nb = wn * 32 + (j2 & 1) * 16 + (j2 >> 1) * 128;
        int n  = nb + (lane & 7) + ((lane >> 4) & 1) * 8;
        int kq = ((lane >> 3) & 1) * 8;
        b_addr[j2] = smem_base + SMEM_W + (uint32_t)(n * 264 + kq) * 2;
    }

    float c[2][8][4];
    #pragma unroll
    for (int i = 0; i < 2; i++)
        #pragma unroll
        for (int j = 0; j < 8; j++)
            #pragma unroll
            for (int e = 0; e < 4; e++) c[i][j][e] = 0.0f;

    // Mainloop: 16 K-steps of k16
    #pragma unroll
    for (int s = 0; s < 16; s++) {
        const uint32_t ko = (uint32_t)s * 32;
        uint32_t ar[2][4], br[4][4];
        #pragma unroll
        for (int i = 0; i < 2; i++)
            LDSM4(ar[i][0], ar[i][1], ar[i][2], ar[i][3], a_addr[i] + ko);
        #pragma unroll
        for (int j2 = 0; j2 < 4; j2++)
            LDSM4(br[j2][0], br[j2][1], br[j2][2], br[j2][3], b_addr[j2] + ko);
        #pragma unroll
        for (int i = 0; i < 2; i++)
            #pragma unroll
            for (int j = 0; j < 8; j++)
                MMA16816(c[i][j], ar[i][0], ar[i][1], ar[i][2], ar[i][3],
                         br[j >> 1][(j & 1) * 2], br[j >> 1][(j & 1) * 2 + 1]);
    }
    __syncthreads();   // SMEM A/W now free; stats region reused below

    // Epilogue: elementwise gate + tanh in registers, row stats via SMEM.
    float* s_bg   = (float*)(smem + SMEM_BG);
    float* s_ba   = (float*)(smem + SMEM_BA);
    float* s_gam  = (float*)(smem + SMEM_GAM);
    float* s_bet  = (float*)(smem + SMEM_BET);
    float* s_psum = (float*)(smem + SMEM_PSUM);
    float* s_psq  = (float*)(smem + SMEM_PSQ);
    float* s_mu   = (float*)(smem + SMEM_MU);
    float* s_rstd = (float*)(smem + SMEM_RSTD);

    float rsum[4] = {0.f, 0.f, 0.f, 0.f};
    float rsq[4]  = {0.f, 0.f, 0.f, 0.f};

    #pragma unroll
    for (int i = 0; i < 2; i++) {
        #pragma unroll
        for (int j = 0; j < 4; j++) {
            const int f0 = wn * 32 + 8 * j + 2 * tig;
            #pragma unroll
            for (int rh = 0; rh < 2; rh++) {
                #pragma unroll
                for (int e = 0; e < 2; e++) {
                    const int f = f0 + e;
                    float gv = c[i][j][rh * 2 + e] + s_bg[f];
                    float zv = c[i][j + 4][rh * 2 + e] + s_ba[f];
                    float al = 0.5f + 0.5f * tanh_fast(0.5f * gv);  // sigmoid
                    float ht = al * tanh_fast(zv) + (1.0f - al) * zv;
                    c[i][j][rh * 2 + e] = ht;
                    rsum[i * 2 + rh] += ht;
                    rsq[i * 2 + rh]  += ht * ht;
                }
            }
        }
    }

    // Quad-reduce (lanes differing in tig hold same row), then SMEM partials.
    #pragma unroll
    for (int r = 0; r < 4; r++) {
        float s = rsum[r], q = rsq[r];
        s += __shfl_xor_sync(0xffffffffu, s, 1);
        q += __shfl_xor_sync(0xffffffffu, q, 1);
        s += __shfl_xor_sync(0xffffffffu, s, 2);
        q += __shfl_xor_sync(0xffffffffu, q, 2);
        if (tig == 0) {
            int row = wm * 32 + 16 * (r >> 1) + 8 * (r & 1) + gq;
            s_psum[row * 4 + wn] = s;
            s_psq[row * 4 + wn]  = q;
        }
    }
    __syncthreads();

    if (tid < 128) {
        float s = s_psum[tid * 4] + s_psum[tid * 4 + 1] +
                  s_psum[tid * 4 + 2] + s_psum[tid * 4 + 3];
        float q = s_psq[tid * 4] + s_psq[tid * 4 + 1] +
                  s_psq[tid * 4 + 2] + s_psq[tid * 4 + 3];
        float mu  = s * (1.0f / 128.0f);
        float var = q * (1.0f / 128.0f) - mu * mu;
        s_mu[tid]   = mu;
        s_rstd[tid] = rsqrtf(var + EPSV);
    }
    __syncthreads();

    // Normalize + store (float2, cols contiguous per quad).
    #pragma unroll
    for (int i = 0; i < 2; i++) {
        #pragma unroll
        for (int rh = 0; rh < 2; rh++) {
            const int row = wm * 32 + 16 * i + 8 * rh + gq;
            const float mu = s_mu[row];
            const float rs = s_rstd[row];
            #pragma unroll
            for (int j = 0; j < 4; j++) {
                const int f0 = wn * 32 + 8 * j + 2 * tig;
                float2 v;
                v.x = (c[i][j][rh * 2 + 0] - mu) * rs * s_gam[f0]     + s_bet[f0];
                v.y = (c[i][j][rh * 2 + 1] - mu) * rs * s_gam[f0 + 1] + s_bet[f0 + 1];
                *(float2*)&out[(size_t)(row0 + row) * 128 + f0] = v;
            }
        }
    }
}

// ---------------------------------------------------------------------------
extern "C" void kernel_launch(void* const* d_in, const int* in_sizes, int n_in,
                              void* d_out, int out_size) {
    const float* x     = (const float*)d_in[0];
    const float* h     = (const float*)d_in[1];
    const float* W_a   = (const float*)d_in[2];
    const float* W_g   = (const float*)d_in[3];
    const float* b_a   = (const float*)d_in[4];
    const float* b_g   = (const float*)d_in[5];
    const float* gamma = (const float*)d_in[6];
    const float* beta  = (const float*)d_in[7];
    float* out = (float*)d_out;

    cudaFuncSetAttribute(adaaff_kernel,
                         cudaFuncAttributeMaxDynamicSharedMemorySize, SMEM_TOTAL);

    prep_w_kernel<<<256, 256>>>(W_a, W_g);
    adaaff_kernel<<<4096, 512, SMEM_TOTAL>>>(x, h, b_a, b_g, gamma, beta, out);
}

// round 5
// speedup vs baseline: 1.1553x; 1.1553x over previous
#include <cuda_runtime.h>
#include <cuda_fp16.h>
#include <cstdint>

// ----------------------------------------------------------------------------
// AdaAffcell, persistent-CTA pipelined version (sm_103 base ISA: HMMA mma.sync).
//   hx = [h, x] (B x 256); g = hx W_g^T + b_g ; z = hx W_a^T + b_a
//   h~ = sigmoid(g)*tanh(z) + (1-sigmoid(g))*z ; out = LN(h~)*gamma + beta
//
// Persistent CTA per SM. W (fp16 [256][264]) loaded into SMEM once per CTA.
// Tiles of 64 rows, A double-buffered; next tile's GMEM loads are issued into
// registers BEFORE the current tile's MMA+epilogue, hiding DRAM latency.
// Warp grid 2x8: wm = 32-row block, wn = 16 g-cols + the matching 16 z-cols,
// so the gated-tanh combine is elementwise in registers.
// ----------------------------------------------------------------------------

#define NROWS  524288
#define TILE   64
#define NTILES (NROWS / TILE)
#define EPSV   1e-5f

// fp16 image of Wcat = [W_g ; W_a], padded stride 264 halves.
__device__ __align__(16) __half g_Wimg[256 * 264];

// SMEM layout (bytes)
#define SMEM_W     0            // fp16 [256][264] = 135168
#define SMEM_A0    135168       // fp16 [64][264]  =  33792
#define SMEM_A1    168960       // fp16 [64][264]  =  33792
#define SMEM_BG    202752       // f32 [128]
#define SMEM_BA    203264
#define SMEM_GAM   203776
#define SMEM_BET   204288
#define SMEM_PSUM  204800       // f32 [64][9] = 2304
#define SMEM_PSQ   207104       // f32 [64][9] = 2304
#define SMEM_MU    209408       // f32 [64]
#define SMEM_RSTD  209664       // f32 [64]
#define SMEM_TOTAL 209920

static __device__ __forceinline__ uint32_t smem_u32(const void* p) {
    uint32_t a;
    asm("{ .reg .u64 t; cvta.to.shared.u64 t, %1; cvt.u32.u64 %0, t; }"
        : "=r"(a) : "l"(p));
    return a;
}

static __device__ __forceinline__ float tanh_fast(float v) {
    float r;
    asm("tanh.approx.f32 %0, %1;" : "=f"(r) : "f"(v));
    return r;
}

#define LDSM4(r0, r1, r2, r3, addr)                                              \
    asm volatile("ldmatrix.sync.aligned.m8n8.x4.shared.b16 {%0,%1,%2,%3}, [%4];" \
                 : "=r"(r0), "=r"(r1), "=r"(r2), "=r"(r3) : "r"(addr))

#define MMA16816(c, a0, a1, a2, a3, b0, b1)                                  \
    asm volatile("mma.sync.aligned.m16n8k16.row.col.f32.f16.f16.f32 "        \
                 "{%0,%1,%2,%3}, {%4,%5,%6,%7}, {%8,%9}, {%0,%1,%2,%3};"     \
                 : "+f"((c)[0]), "+f"((c)[1]), "+f"((c)[2]), "+f"((c)[3])    \
                 : "r"(a0), "r"(a1), "r"(a2), "r"(a3), "r"(b0), "r"(b1))

// ---------------------------------------------------------------------------
__global__ void prep_w_kernel(const float* __restrict__ Wa, const float* __restrict__ Wg) {
    int i = blockIdx.x * 256 + threadIdx.x;   // 0..65535
    int n = i >> 8;
    int k = i & 255;
    float v = (n < 128) ? Wg[n * 256 + k] : Wa[(n - 128) * 256 + k];
    g_Wimg[n * 264 + k] = __float2half_rn(v);
}

// ---------------------------------------------------------------------------
__global__ void __launch_bounds__(512, 1) adaaff_kernel(
    const float* __restrict__ x, const float* __restrict__ h,
    const float* __restrict__ b_a, const float* __restrict__ b_g,
    const float* __restrict__ gamma, const float* __restrict__ beta,
    float* __restrict__ out)
{
    extern __shared__ __align__(16) char smem[];
    const uint32_t smem_base = smem_u32(smem);
    const int tid  = threadIdx.x;
    const int lane = tid & 31;
    const int wid  = tid >> 5;
    const int wm   = wid & 1;      // 32-row block
    const int wn   = wid >> 1;     // 16-feature block (0..7)
    const int tig  = lane & 3;
    const int gq   = lane >> 2;

    // ---- one-time setup: vectors + W tile ----
    if (tid < 128) {
        *(float*)(smem + SMEM_BG  + tid * 4) = b_g[tid];
        *(float*)(smem + SMEM_BA  + tid * 4) = b_a[tid];
        *(float*)(smem + SMEM_GAM + tid * 4) = gamma[tid];
        *(float*)(smem + SMEM_BET + tid * 4) = beta[tid];
    }
    {
        const uint4* src = (const uint4*)g_Wimg;
        uint4* dst = (uint4*)(smem + SMEM_W);
        for (int i = tid; i < 8448; i += 512) dst[i] = src[i];
    }

    // per-thread staging coords: i = tid + j*512 -> m = i>>5, k0 = (i&31)*4
    const int sm0 = tid >> 5;          // j contributes +16 rows per step
    const int sk0 = (tid & 31) << 2;

    float4 rh4[4], rx4[4];

    // ---- prologue: load + store tile #blockIdx.x into buffer 0 ----
    int tile = blockIdx.x;
    if (tile < NTILES) {
        const size_t r0 = (size_t)tile * TILE;
        #pragma unroll
        for (int j = 0; j < 4; j++) {
            const size_t m = r0 + sm0 + j * 16;
            rh4[j] = *(const float4*)&h[m * 128 + sk0];
            rx4[j] = *(const float4*)&x[m * 128 + sk0];
        }
        __half* sA = (__half*)(smem + SMEM_A0);
        #pragma unroll
        for (int j = 0; j < 4; j++) {
            const int m = sm0 + j * 16;
            __half2 p0 = __floats2half2_rn(rh4[j].x, rh4[j].y);
            __half2 p1 = __floats2half2_rn(rh4[j].z, rh4[j].w);
            *(uint2*)&sA[m * 264 + sk0] = make_uint2(*(uint32_t*)&p0, *(uint32_t*)&p1);
            __half2 q0 = __floats2half2_rn(rx4[j].x, rx4[j].y);
            __half2 q1 = __floats2half2_rn(rx4[j].z, rx4[j].w);
            *(uint2*)&sA[m * 264 + 128 + sk0] = make_uint2(*(uint32_t*)&q0, *(uint32_t*)&q1);
        }
    }
    __syncthreads();

    // ldmatrix lane addressing (A base varies per buffer; B fixed)
    uint32_t a_off[2];
    #pragma unroll
    for (int i = 0; i < 2; i++) {
        int r  = wm * 32 + 16 * i + (lane & 15);
        int kq = (lane >> 4) * 8;
        a_off[i] = (uint32_t)(r * 264 + kq) * 2;
    }
    uint32_t b_addr[2];
    #pragma unroll
    for (int j2 = 0; j2 < 2; j2++) {
        int nb = wn * 16 + j2 * 128;
        int n  = nb + (lane & 7) + ((lane >> 4) & 1) * 8;
        int kq = ((lane >> 3) & 1) * 8;
        b_addr[j2] = smem_base + SMEM_W + (uint32_t)(n * 264 + kq) * 2;
    }

    float* s_bg   = (float*)(smem + SMEM_BG);
    float* s_ba   = (float*)(smem + SMEM_BA);
    float* s_gam  = (float*)(smem + SMEM_GAM);
    float* s_bet  = (float*)(smem + SMEM_BET);
    float* s_psum = (float*)(smem + SMEM_PSUM);
    float* s_psq  = (float*)(smem + SMEM_PSQ);
    float* s_mu   = (float*)(smem + SMEM_MU);
    float* s_rstd = (float*)(smem + SMEM_RSTD);

    int p = 0;
    while (tile < NTILES) {
        const int ntile = tile + gridDim.x;
        const bool has_next = (ntile < NTILES);

        // ---- 1. issue next tile's GMEM loads (latency hidden by MMA below) ----
        if (has_next) {
            const size_t r0 = (size_t)ntile * TILE;
            #pragma unroll
            for (int j = 0; j < 4; j++) {
                const size_t m = r0 + sm0 + j * 16;
                rh4[j] = *(const float4*)&h[m * 128 + sk0];
                rx4[j] = *(const float4*)&x[m * 128 + sk0];
            }
        }

        // ---- 2. MMA on current buffer ----
        const uint32_t a_base = smem_base + (p ? SMEM_A1 : SMEM_A0);
        float c[2][4][4];
        #pragma unroll
        for (int i = 0; i < 2; i++)
            #pragma unroll
            for (int j = 0; j < 4; j++)
                #pragma unroll
                for (int e = 0; e < 4; e++) c[i][j][e] = 0.0f;

        #pragma unroll
        for (int s = 0; s < 16; s++) {
            const uint32_t ko = (uint32_t)s * 32;
            uint32_t ar[2][4], br[2][4];
            #pragma unroll
            for (int i = 0; i < 2; i++)
                LDSM4(ar[i][0], ar[i][1], ar[i][2], ar[i][3], a_base + a_off[i] + ko);
            #pragma unroll
            for (int j2 = 0; j2 < 2; j2++)
                LDSM4(br[j2][0], br[j2][1], br[j2][2], br[j2][3], b_addr[j2] + ko);
            #pragma unroll
            for (int i = 0; i < 2; i++)
                #pragma unroll
                for (int j = 0; j < 4; j++)
                    MMA16816(c[i][j], ar[i][0], ar[i][1], ar[i][2], ar[i][3],
                             br[j >> 1][(j & 1) * 2], br[j >> 1][(j & 1) * 2 + 1]);
        }

        // ---- 3. epilogue: gate+tanh in regs, row stats via SMEM ----
        float rsum[4] = {0.f, 0.f, 0.f, 0.f};
        float rsq[4]  = {0.f, 0.f, 0.f, 0.f};
        #pragma unroll
        for (int i = 0; i < 2; i++) {
            #pragma unroll
            for (int j = 0; j < 2; j++) {
                const int f0 = wn * 16 + j * 8 + 2 * tig;
                #pragma unroll
                for (int rh = 0; rh < 2; rh++) {
                    #pragma unroll
                    for (int e = 0; e < 2; e++) {
                        const int f = f0 + e;
                        float gv = c[i][j][rh * 2 + e] + s_bg[f];
                        float zv = c[i][j + 2][rh * 2 + e] + s_ba[f];
                        float al = 0.5f + 0.5f * tanh_fast(0.5f * gv);   // sigmoid
                        float ht = al * tanh_fast(zv) + (1.0f - al) * zv;
                        c[i][j][rh * 2 + e] = ht;
                        rsum[i * 2 + rh] += ht;
                        rsq[i * 2 + rh]  += ht * ht;
                    }
                }
            }
        }
        #pragma unroll
        for (int r = 0; r < 4; r++) {
            float sv = rsum[r], qv = rsq[r];
            sv += __shfl_xor_sync(0xffffffffu, sv, 1);
            qv += __shfl_xor_sync(0xffffffffu, qv, 1);
            sv += __shfl_xor_sync(0xffffffffu, sv, 2);
            qv += __shfl_xor_sync(0xffffffffu, qv, 2);
            if (tig == 0) {
                const int rowl = wm * 32 + 16 * (r >> 1) + 8 * (r & 1) + gq;
                s_psum[rowl * 9 + wn] = sv;
                s_psq[rowl * 9 + wn]  = qv;
            }
        }
        __syncthreads();

        if (tid < 64) {
            float sv = 0.f, qv = 0.f;
            #pragma unroll
            for (int w = 0; w < 8; w++) { sv += s_psum[tid * 9 + w]; qv += s_psq[tid * 9 + w]; }
            const float mu  = sv * (1.0f / 128.0f);
            const float var = qv * (1.0f / 128.0f) - mu * mu;
            s_mu[tid]   = mu;
            s_rstd[tid] = rsqrtf(var + EPSV);
        }
        __syncthreads();

        // normalize + store
        {
            const size_t r0 = (size_t)tile * TILE;
            #pragma unroll
            for (int i = 0; i < 2; i++) {
                #pragma unroll
                for (int rh = 0; rh < 2; rh++) {
                    const int rowl = wm * 32 + 16 * i + 8 * rh + gq;
                    const float mu = s_mu[rowl];
                    const float rs = s_rstd[rowl];
                    #pragma unroll
                    for (int j = 0; j < 2; j++) {
                        const int f0 = wn * 16 + j * 8 + 2 * tig;
                        float2 v;
                        v.x = (c[i][j][rh * 2 + 0] - mu) * rs * s_gam[f0]     + s_bet[f0];
                        v.y = (c[i][j][rh * 2 + 1] - mu) * rs * s_gam[f0 + 1] + s_bet[f0 + 1];
                        *(float2*)&out[(r0 + rowl) * 128 + f0] = v;
                    }
                }
            }
        }

        // ---- 4. convert + store staged regs into the spare buffer ----
        if (has_next) {
            __half* sA = (__half*)(smem + (p ? SMEM_A0 : SMEM_A1));
            #pragma unroll
            for (int j = 0; j < 4; j++) {
                const int m = sm0 + j * 16;
                __half2 p0 = __floats2half2_rn(rh4[j].x, rh4[j].y);
                __half2 p1 = __floats2half2_rn(rh4[j].z, rh4[j].w);
                *(uint2*)&sA[m * 264 + sk0] = make_uint2(*(uint32_t*)&p0, *(uint32_t*)&p1);
                __half2 q0 = __floats2half2_rn(rx4[j].x, rx4[j].y);
                __half2 q1 = __floats2half2_rn(rx4[j].z, rx4[j].w);
                *(uint2*)&sA[m * 264 + 128 + sk0] = make_uint2(*(uint32_t*)&q0, *(uint32_t*)&q1);
            }
        }
        __syncthreads();

        p ^= 1;
        tile = ntile;
    }
}

// ---------------------------------------------------------------------------
extern "C" void kernel_launch(void* const* d_in, const int* in_sizes, int n_in,
                              void* d_out, int out_size) {
    const float* x     = (const float*)d_in[0];
    const float* h     = (const float*)d_in[1];
    const float* W_a   = (const float*)d_in[2];
    const float* W_g   = (const float*)d_in[3];
    const float* b_a   = (const float*)d_in[4];
    const float* b_g   = (const float*)d_in[5];
    const float* gamma = (const float*)d_in[6];
    const float* beta  = (const float*)d_in[7];
    float* out = (float*)d_out;

    // SM count queried once (function-local static: no repeated device queries
    // inside graph capture/replay; still deterministic).
    static int nsm = 0;
    if (nsm == 0) {
        int dev = 0, v = 0;
        nsm = 148;
        if (cudaGetDevice(&dev) == cudaSuccess &&
            cudaDeviceGetAttribute(&v, cudaDevAttrMultiProcessorCount, dev) == cudaSuccess &&
            v > 0)
            nsm = v;
        cudaFuncSetAttribute(adaaff_kernel,
                             cudaFuncAttributeMaxDynamicSharedMemorySize, SMEM_TOTAL);
    }

    prep_w_kernel<<<256, 256>>>(W_a, W_g);
    adaaff_kernel<<<nsm, 512, SMEM_TOTAL>>>(x, h, b_a, b_g, gamma, beta, out);
}

// round 6
// speedup vs baseline: 1.2176x; 1.0540x over previous
#include <cuda_runtime.h>
#include <cuda_fp16.h>
#include <cstdint>

// ----------------------------------------------------------------------------
// AdaAffcell, persistent-CTA pipelined (sm_103 base ISA: HMMA mma.sync).
//   hx = [h, x] (B x 256); g = hx W_g^T + b_g ; z = hx W_a^T + b_a
//   h~ = sigmoid(g)*tanh(z) + (1-sigmoid(g))*z ; out = LN(h~)*gamma + beta
//
// Persistent CTA per SM, W in SMEM once. 64-row tiles, A double-buffered with
// register staging. 256 threads / 8 warps, warp grid (wm=2, wn=4):
// warp = 32 rows x (32 g-cols + 32 matching z-cols) -> 64 acc regs, halved
// A-fragment redundancy vs 16-warp layout, 16 independent MMAs per k-step.
// ----------------------------------------------------------------------------

#define NROWS  524288
#define TILE   64
#define NTILES (NROWS / TILE)
#define EPSV   1e-5f

// fp16 image of Wcat = [W_g ; W_a], padded stride 264 halves.
__device__ __align__(16) __half g_Wimg[256 * 264];

// SMEM layout (bytes)
#define SMEM_W     0            // fp16 [256][264] = 135168
#define SMEM_A0    135168       // fp16 [64][264]  =  33792
#define SMEM_A1    168960       // fp16 [64][264]  =  33792
#define SMEM_BG    202752       // f32 [128]
#define SMEM_BA    203264
#define SMEM_GAM   203776
#define SMEM_BET   204288
#define SMEM_PSUM  204800       // f32 [64][5] = 1280
#define SMEM_PSQ   206080       // f32 [64][5] = 1280
#define SMEM_MU    207360       // f32 [64]
#define SMEM_RSTD  207616       // f32 [64]
#define SMEM_TOTAL 207872

static __device__ __forceinline__ uint32_t smem_u32(const void* p) {
    uint32_t a;
    asm("{ .reg .u64 t; cvta.to.shared.u64 t, %1; cvt.u32.u64 %0, t; }"
        : "=r"(a) : "l"(p));
    return a;
}

static __device__ __forceinline__ float tanh_fast(float v) {
    float r;
    asm("tanh.approx.f32 %0, %1;" : "=f"(r) : "f"(v));
    return r;
}

#define LDSM4(r0, r1, r2, r3, addr)                                              \
    asm volatile("ldmatrix.sync.aligned.m8n8.x4.shared.b16 {%0,%1,%2,%3}, [%4];" \
                 : "=r"(r0), "=r"(r1), "=r"(r2), "=r"(r3) : "r"(addr))

#define MMA16816(c, a0, a1, a2, a3, b0, b1)                                  \
    asm volatile("mma.sync.aligned.m16n8k16.row.col.f32.f16.f16.f32 "        \
                 "{%0,%1,%2,%3}, {%4,%5,%6,%7}, {%8,%9}, {%0,%1,%2,%3};"     \
                 : "+f"((c)[0]), "+f"((c)[1]), "+f"((c)[2]), "+f"((c)[3])    \
                 : "r"(a0), "r"(a1), "r"(a2), "r"(a3), "r"(b0), "r"(b1))

// ---------------------------------------------------------------------------
__global__ void prep_w_kernel(const float* __restrict__ Wa, const float* __restrict__ Wg) {
    int i = blockIdx.x * 256 + threadIdx.x;   // 0..65535
    int n = i >> 8;
    int k = i & 255;
    float v = (n < 128) ? Wg[n * 256 + k] : Wa[(n - 128) * 256 + k];
    g_Wimg[n * 264 + k] = __float2half_rn(v);
}

// ---------------------------------------------------------------------------
__global__ void __launch_bounds__(256, 1) adaaff_kernel(
    const float* __restrict__ x, const float* __restrict__ h,
    const float* __restrict__ b_a, const float* __restrict__ b_g,
    const float* __restrict__ gamma, const float* __restrict__ beta,
    float* __restrict__ out)
{
    extern __shared__ __align__(16) char smem[];
    const uint32_t smem_base = smem_u32(smem);
    const int tid  = threadIdx.x;
    const int lane = tid & 31;
    const int wid  = tid >> 5;
    const int wm   = wid & 1;      // 32-row block
    const int wn   = wid >> 1;     // 32-feature block (0..3)
    const int tig  = lane & 3;
    const int gq   = lane >> 2;

    // ---- one-time setup: vectors + W tile ----
    if (tid < 128) {
        *(float*)(smem + SMEM_BG  + tid * 4) = b_g[tid];
        *(float*)(smem + SMEM_BA  + tid * 4) = b_a[tid];
        *(float*)(smem + SMEM_GAM + tid * 4) = gamma[tid];
        *(float*)(smem + SMEM_BET + tid * 4) = beta[tid];
    }
    {
        const uint4* src = (const uint4*)g_Wimg;
        uint4* dst = (uint4*)(smem + SMEM_W);
        for (int i = tid; i < 8448; i += 256) dst[i] = src[i];
    }

    // staging coords: i = tid + j*256 -> m = (tid>>5) + j*8, k0 = (tid&31)*4
    const int sm0 = tid >> 5;
    const int sk0 = (tid & 31) << 2;

    float4 rh4[8], rx4[8];

    // ---- prologue: load + store tile #blockIdx.x into buffer 0 ----
    int tile = blockIdx.x;
    if (tile < NTILES) {
        const size_t r0 = (size_t)tile * TILE;
        #pragma unroll
        for (int j = 0; j < 8; j++) {
            const size_t m = r0 + sm0 + j * 8;
            rh4[j] = *(const float4*)&h[m * 128 + sk0];
            rx4[j] = *(const float4*)&x[m * 128 + sk0];
        }
        __half* sA = (__half*)(smem + SMEM_A0);
        #pragma unroll
        for (int j = 0; j < 8; j++) {
            const int m = sm0 + j * 8;
            __half2 p0 = __floats2half2_rn(rh4[j].x, rh4[j].y);
            __half2 p1 = __floats2half2_rn(rh4[j].z, rh4[j].w);
            *(uint2*)&sA[m * 264 + sk0] = make_uint2(*(uint32_t*)&p0, *(uint32_t*)&p1);
            __half2 q0 = __floats2half2_rn(rx4[j].x, rx4[j].y);
            __half2 q1 = __floats2half2_rn(rx4[j].z, rx4[j].w);
            *(uint2*)&sA[m * 264 + 128 + sk0] = make_uint2(*(uint32_t*)&q0, *(uint32_t*)&q1);
        }
    }
    __syncthreads();

    // ldmatrix lane addressing.
    // A: m16k16 fragment, rows wm*32 + 16*i
    uint32_t a_off[2];
    #pragma unroll
    for (int i = 0; i < 2; i++) {
        int r  = wm * 32 + 16 * i + (lane & 15);
        int kq = (lane >> 4) * 8;
        a_off[i] = (uint32_t)(r * 264 + kq) * 2;
    }
    // B: n16k16 fragments. j2=0,1 -> g cols (wn*32 + j2*16); j2=2,3 -> z cols (+128)
    uint32_t b_addr[4];
    #pragma unroll
    for (int j2 = 0; j2 < 4; j2++) {
        int nb = wn * 32 + (j2 & 1) * 16 + (j2 >> 1) * 128;
        int n  = nb + (lane & 7) + ((lane >> 4) & 1) * 8;
        int kq = ((lane >> 3) & 1) * 8;
        b_addr[j2] = smem_base + SMEM_W + (uint32_t)(n * 264 + kq) * 2;
    }

    float* s_bg   = (float*)(smem + SMEM_BG);
    float* s_ba   = (float*)(smem + SMEM_BA);
    float* s_gam  = (float*)(smem + SMEM_GAM);
    float* s_bet  = (float*)(smem + SMEM_BET);
    float* s_psum = (float*)(smem + SMEM_PSUM);
    float* s_psq  = (float*)(smem + SMEM_PSQ);
    float* s_mu   = (float*)(smem + SMEM_MU);
    float* s_rstd = (float*)(smem + SMEM_RSTD);

    int p = 0;
    while (tile < NTILES) {
        const int ntile = tile + gridDim.x;
        const bool has_next = (ntile < NTILES);

        // ---- 1. issue next tile's GMEM loads ----
        if (has_next) {
            const size_t r0 = (size_t)ntile * TILE;
            #pragma unroll
            for (int j = 0; j < 8; j++) {
                const size_t m = r0 + sm0 + j * 8;
                rh4[j] = *(const float4*)&h[m * 128 + sk0];
                rx4[j] = *(const float4*)&x[m * 128 + sk0];
            }
        }

        // ---- 2. MMA on current buffer ----
        // c[i][j]: i = m16 block; j 0..3 = g n8 blocks, j 4..7 = matching z
        const uint32_t a_base = smem_base + (p ? SMEM_A1 : SMEM_A0);
        float c[2][8][4];
        #pragma unroll
        for (int i = 0; i < 2; i++)
            #pragma unroll
            for (int j = 0; j < 8; j++)
                #pragma unroll
                for (int e = 0; e < 4; e++) c[i][j][e] = 0.0f;

        #pragma unroll
        for (int s = 0; s < 16; s++) {
            const uint32_t ko = (uint32_t)s * 32;
            uint32_t ar[2][4], br[4][4];
            #pragma unroll
            for (int i = 0; i < 2; i++)
                LDSM4(ar[i][0], ar[i][1], ar[i][2], ar[i][3], a_base + a_off[i] + ko);
            #pragma unroll
            for (int j2 = 0; j2 < 4; j2++)
                LDSM4(br[j2][0], br[j2][1], br[j2][2], br[j2][3], b_addr[j2] + ko);
            // j 0..3 -> g (j2 = j>>1), j 4..7 -> z (j2 = 2 + ((j-4)>>1))
            #pragma unroll
            for (int i = 0; i < 2; i++) {
                #pragma unroll
                for (int j = 0; j < 8; j++) {
                    const int j2  = (j >> 2) * 2 + ((j & 3) >> 1);
                    const int sub = (j & 1) * 2;
                    MMA16816(c[i][j], ar[i][0], ar[i][1], ar[i][2], ar[i][3],
                             br[j2][sub], br[j2][sub + 1]);
                }
            }
        }

        // ---- 3. publish next A tile into spare buffer (before stats barrier) ----
        if (has_next) {
            __half* sA = (__half*)(smem + (p ? SMEM_A0 : SMEM_A1));
            #pragma unroll
            for (int j = 0; j < 8; j++) {
                const int m = sm0 + j * 8;
                __half2 p0 = __floats2half2_rn(rh4[j].x, rh4[j].y);
                __half2 p1 = __floats2half2_rn(rh4[j].z, rh4[j].w);
                *(uint2*)&sA[m * 264 + sk0] = make_uint2(*(uint32_t*)&p0, *(uint32_t*)&p1);
                __half2 q0 = __floats2half2_rn(rx4[j].x, rx4[j].y);
                __half2 q1 = __floats2half2_rn(rx4[j].z, rx4[j].w);
                *(uint2*)&sA[m * 264 + 128 + sk0] = make_uint2(*(uint32_t*)&q0, *(uint32_t*)&q1);
            }
        }

        // ---- 4. epilogue: gate+tanh in regs, row stats via SMEM ----
        float rsum[4] = {0.f, 0.f, 0.f, 0.f};
        float rsq[4]  = {0.f, 0.f, 0.f, 0.f};
        #pragma unroll
        for (int i = 0; i < 2; i++) {
            #pragma unroll
            for (int j = 0; j < 4; j++) {
                const int f0 = wn * 32 + j * 8 + 2 * tig;
                #pragma unroll
                for (int rh = 0; rh < 2; rh++) {
                    #pragma unroll
                    for (int e = 0; e < 2; e++) {
                        const int f = f0 + e;
                        float gv = c[i][j][rh * 2 + e] + s_bg[f];
                        float zv = c[i][j + 4][rh * 2 + e] + s_ba[f];
                        float al = 0.5f + 0.5f * tanh_fast(0.5f * gv);   // sigmoid
                        float ht = al * tanh_fast(zv) + (1.0f - al) * zv;
                        c[i][j][rh * 2 + e] = ht;
                        rsum[i * 2 + rh] += ht;
                        rsq[i * 2 + rh]  += ht * ht;
                    }
                }
            }
        }
        #pragma unroll
        for (int r = 0; r < 4; r++) {
            float sv = rsum[r], qv = rsq[r];
            sv += __shfl_xor_sync(0xffffffffu, sv, 1);
            qv += __shfl_xor_sync(0xffffffffu, qv, 1);
            sv += __shfl_xor_sync(0xffffffffu, sv, 2);
            qv += __shfl_xor_sync(0xffffffffu, qv, 2);
            if (tig == 0) {
                const int rowl = wm * 32 + 16 * (r >> 1) + 8 * (r & 1) + gq;
                s_psum[rowl * 5 + wn] = sv;
                s_psq[rowl * 5 + wn]  = qv;
            }
        }
        __syncthreads();          // covers psum/psq AND spare-A publication

        if (tid < 64) {
            float sv = 0.f, qv = 0.f;
            #pragma unroll
            for (int w = 0; w < 4; w++) { sv += s_psum[tid * 5 + w]; qv += s_psq[tid * 5 + w]; }
            const float mu  = sv * (1.0f / 128.0f);
            const float var = qv * (1.0f / 128.0f) - mu * mu;
            s_mu[tid]   = mu;
            s_rstd[tid] = rsqrtf(var + EPSV);
        }
        __syncthreads();

        // normalize + store
        {
            const size_t r0 = (size_t)tile * TILE;
            #pragma unroll
            for (int i = 0; i < 2; i++) {
                #pragma unroll
                for (int rh = 0; rh < 2; rh++) {
                    const int rowl = wm * 32 + 16 * i + 8 * rh + gq;
                    const float mu = s_mu[rowl];
                    const float rs = s_rstd[rowl];
                    #pragma unroll
                    for (int j = 0; j < 4; j++) {
                        const int f0 = wn * 32 + j * 8 + 2 * tig;
                        float2 v;
                        v.x = (c[i][j][rh * 2 + 0] - mu) * rs * s_gam[f0]     + s_bet[f0];
                        v.y = (c[i][j][rh * 2 + 1] - mu) * rs * s_gam[f0 + 1] + s_bet[f0 + 1];
                        *(float2*)&out[(r0 + rowl) * 128 + f0] = v;
                    }
                }
            }
        }

        p ^= 1;
        tile = ntile;
    }
}

// ---------------------------------------------------------------------------
extern "C" void kernel_launch(void* const* d_in, const int* in_sizes, int n_in,
                              void* d_out, int out_size) {
    const float* x     = (const float*)d_in[0];
    const float* h     = (const float*)d_in[1];
    const float* W_a   = (const float*)d_in[2];
    const float* W_g   = (const float*)d_in[3];
    const float* b_a   = (const float*)d_in[4];
    const float* b_g   = (const float*)d_in[5];
    const float* gamma = (const float*)d_in[6];
    const float* beta  = (const float*)d_in[7];
    float* out = (float*)d_out;

    static int nsm = 0;
    if (nsm == 0) {
        int dev = 0, v = 0;
        nsm = 148;
        if (cudaGetDevice(&dev) == cudaSuccess &&
            cudaDeviceGetAttribute(&v, cudaDevAttrMultiProcessorCount, dev) == cudaSuccess &&
            v > 0)
            nsm = v;
        cudaFuncSetAttribute(adaaff_kernel,
                             cudaFuncAttributeMaxDynamicSharedMemorySize, SMEM_TOTAL);
    }

    prep_w_kernel<<<256, 256>>>(W_a, W_g);
    adaaff_kernel<<<nsm, 256, SMEM_TOTAL>>>(x, h, b_a, b_g, gamma, beta, out);
}